// round 13
// baseline (speedup 1.0000x reference)
#include <cuda_runtime.h>
#include <math.h>

// Problem-fixed: N_TRAIN=131072, M_TEST=65536
#define TT     196608
#define LOGC   6
#define CHUNK  64
#define NCH    (TT / CHUNK)   // 3072
#define WARM   2048

// Transposed merged inputs: index (j, chunk) -> j*NCH + chunk. (t, residual, R, is_obs)
__device__ float4 g_in_t[(size_t)CHUNK * NCH];
__device__ int    g_tj[TT];
// Precomputed per-slot transition pack, SoA-transposed (3 fields):
//  F0=(A00,A01,A02,A10)  F1=(A11,A12,A20,A21)  F2=(A22, r, R, obs)
__device__ float4 g_Am[(size_t)3 * CHUNK * NCH];
// Slim smoother record, SoA-transposed (4 fields):
//  F0=(G00,G01,G02,G10)  F1=(G11,G12,G20,G21)  F2=(G22,w0,w1,w2)  F3=(K0,K1,K2,S)
// Fields of slot q written at forward step q+1 (w/K/S via one-step-delayed carries).
// Slot TT-1: F2/F3 written specially at step TT-1 (its G fields never read).
__device__ float4 g_rec[(size_t)4 * CHUNK * NCH];
// Per-slot (m_f[0], P_f[00]) for output reconstruction, payload-read only.
__device__ float2 g_mfP[(size_t)TT];

__device__ __forceinline__ size_t ridx(int f, int slot) {
    int c = slot >> LOGC, j = slot & (CHUNK - 1);
    return ((size_t)(f * CHUNK + j)) * NCH + c;
}
__device__ __forceinline__ size_t iidx(int k) {
    return (size_t)(k & (CHUNK - 1)) * NCH + (k >> LOGC);
}

__global__ void merge_kernel(const float* __restrict__ times, const float* __restrict__ tstar,
                             const float* __restrict__ n1, const float* __restrict__ n2,
                             const float* __restrict__ pmc, int N, int M) {
    int i = blockIdx.x * blockDim.x + threadIdx.x;
    if (i < N) {
        float x = times[i];
        // stable argsort: equal keys keep train first -> position = i + #{tstar < x}
        int lo = 0, hi = M;
        while (lo < hi) { int mid = (lo + hi) >> 1; if (tstar[mid] < x) lo = mid + 1; else hi = mid; }
        int p = i + lo;
        float s2 = n2[i];
        float mc = *pmc;
        g_in_t[iidx(p)] = make_float4(x, n1[i] / s2 - mc, 1.0f / s2, 1.0f);
        g_tj[p] = -1;
    } else if (i < N + M) {
        int j = i - N;
        float x = tstar[j];
        // position = j + #{times <= x}
        int lo = 0, hi = N;
        while (lo < hi) { int mid = (lo + hi) >> 1; if (times[mid] <= x) lo = mid + 1; else hi = mid; }
        int p = j + lo;
        g_in_t[iidx(p)] = make_float4(x, 0.0f, 1.0f, 0.0f);
        g_tj[p] = j;
    }
}

// Fully parallel A(dt) precompute: one thread per merged slot.
__global__ void amat_kernel(const float* __restrict__ pls) {
    int k = blockIdx.x * blockDim.x + threadIdx.x;
    if (k >= TT) return;
    float lam = sqrtf(5.0f) / (*pls);
    float lam2 = lam * lam, lam3 = lam2 * lam, lam4 = lam2 * lam2;
    float4 in = g_in_t[iidx(k)];
    float dt = 0.0f;
    if (k > 0) dt = in.x - g_in_t[iidx(k - 1)].x;
    float ed = __expf(-lam * dt);
    float d2 = 0.5f * dt * dt;
    float A00 = ed * (1.0f + dt * lam + d2 * lam2);
    float A01 = ed * (dt + d2 * (2.0f * lam));
    float A02 = ed * d2;
    float A10 = ed * (-d2 * lam3);
    float A11 = ed * (1.0f + dt * lam - d2 * (2.0f * lam2));
    float A12 = ed * (dt - d2 * lam);
    float A20 = ed * (-dt * lam3 + d2 * lam4);
    float A21 = ed * (-3.0f * dt * lam2 + d2 * (2.0f * lam3));
    float A22 = ed * (1.0f - 2.0f * dt * lam + d2 * lam2);
    g_Am[ridx(0, k)] = make_float4(A00, A01, A02, A10);
    g_Am[ridx(1, k)] = make_float4(A11, A12, A20, A21);
    g_Am[ridx(2, k)] = make_float4(A22, in.y, in.z, in.w);
}

// One filter step (A loaded from table, 2-deep pipeline a*/b*).
// STORE==1: compute G for slot k-1, store record fields; store g_mfP[k].
#define FWD_STEP(STORE)                                                          \
    {                                                                            \
        float4 cA0 = a0, cA1 = a1, cA2 = a2;                                     \
        a0 = b0; a1 = b1; a2 = b2;                                               \
        { int kq = min(k + 2, TT - 1);                                           \
          b0 = g_Am[ridx(0, kq)]; b1 = g_Am[ridx(1, kq)];                        \
          b2 = g_Am[ridx(2, kq)]; }                                              \
        float A00 = cA0.x, A01 = cA0.y, A02 = cA0.z, A10 = cA0.w;                \
        float A11 = cA1.x, A12 = cA1.y, A20 = cA1.z, A21 = cA1.w;                \
        float A22 = cA2.x, r = cA2.y, R = cA2.z, obs = cA2.w;                    \
        float D00 = P00 - pi00, D01 = P01, D02 = P02 - pi02;                     \
        float D11 = P11 - pi11, D12 = P12, D22 = P22 - pi22;                     \
        float C00 = A00 * D00 + A01 * D01 + A02 * D02;                           \
        float C01 = A00 * D01 + A01 * D11 + A02 * D12;                           \
        float C02 = A00 * D02 + A01 * D12 + A02 * D22;                           \
        float C10 = A10 * D00 + A11 * D01 + A12 * D02;                           \
        float C11 = A10 * D01 + A11 * D11 + A12 * D12;                           \
        float C12 = A10 * D02 + A11 * D12 + A12 * D22;                           \
        float C20 = A20 * D00 + A21 * D01 + A22 * D02;                           \
        float C21 = A20 * D01 + A21 * D11 + A22 * D12;                           \
        float C22 = A20 * D02 + A21 * D12 + A22 * D22;                           \
        float Pp00 = C00 * A00 + C01 * A01 + C02 * A02 + pi00;                   \
        float Pp01 = C00 * A10 + C01 * A11 + C02 * A12;                          \
        float Pp02 = C00 * A20 + C01 * A21 + C02 * A22 + pi02;                   \
        float Pp11 = C10 * A10 + C11 * A11 + C12 * A12 + pi11;                   \
        float Pp12 = C10 * A20 + C11 * A21 + C12 * A22;                          \
        float Pp22 = C20 * A20 + C21 * A21 + C22 * A22 + pi22;                   \
        float mp0 = A00 * m0 + A01 * m1 + A02 * m2;                              \
        float mp1 = A10 * m0 + A11 * m1 + A12 * m2;                              \
        float mp2 = A20 * m0 + A21 * m1 + A22 * m2;                              \
        if (STORE) {                                                             \
            if (k > 0) {                                                         \
                float AP00 = C00 + A00 * pi00 + A02 * pi02;                      \
                float AP01 = C01 + A01 * pi11;                                   \
                float AP02 = C02 + A00 * pi02 + A02 * pi22;                      \
                float AP10 = C10 + A10 * pi00 + A12 * pi02;                      \
                float AP11 = C11 + A11 * pi11;                                   \
                float AP12 = C12 + A10 * pi02 + A12 * pi22;                      \
                float AP20 = C20 + A20 * pi00 + A22 * pi02;                      \
                float AP21 = C21 + A21 * pi11;                                   \
                float AP22 = C22 + A20 * pi02 + A22 * pi22;                      \
                float i00 = Pp11 * Pp22 - Pp12 * Pp12;                           \
                float i01 = Pp02 * Pp12 - Pp01 * Pp22;                           \
                float i02 = Pp01 * Pp12 - Pp02 * Pp11;                           \
                float i11 = Pp00 * Pp22 - Pp02 * Pp02;                           \
                float i12 = Pp01 * Pp02 - Pp00 * Pp12;                           \
                float i22 = Pp00 * Pp11 - Pp01 * Pp01;                           \
                float det = Pp00 * i00 + Pp01 * i01 + Pp02 * i02;                \
                float idet = __fdividef(1.0f, det);                              \
                i00 *= idet; i01 *= idet; i02 *= idet;                           \
                i11 *= idet; i12 *= idet; i22 *= idet;                           \
                float G00 = AP00 * i00 + AP10 * i01 + AP20 * i02;                \
                float G01 = AP00 * i01 + AP10 * i11 + AP20 * i12;                \
                float G02 = AP00 * i02 + AP10 * i12 + AP20 * i22;                \
                float G10 = AP01 * i00 + AP11 * i01 + AP21 * i02;                \
                float G11 = AP01 * i01 + AP11 * i11 + AP21 * i12;                \
                float G12 = AP01 * i02 + AP11 * i12 + AP21 * i22;                \
                float G20 = AP02 * i00 + AP12 * i01 + AP22 * i02;                \
                float G21 = AP02 * i01 + AP12 * i11 + AP22 * i12;                \
                float G22 = AP02 * i02 + AP12 * i12 + AP22 * i22;                \
                int q = k - 1;                                                   \
                g_rec[ridx(0, q)] = make_float4(G00, G01, G02, G10);             \
                g_rec[ridx(1, q)] = make_float4(G11, G12, G20, G21);             \
                g_rec[ridx(2, q)] = make_float4(G22, pw0, pw1, pw2);             \
                g_rec[ridx(3, q)] = make_float4(pK0, pK1, pK2, pS);              \
            }                                                                    \
        }                                                                        \
        float S = Pp00 + R;                                                      \
        float iS = __fdividef(obs, S);                                           \
        float K0 = Pp00 * iS, K1 = Pp01 * iS, K2 = Pp02 * iS;                    \
        float v = r - mp0;                                                       \
        float w0 = K0 * v, w1 = K1 * v, w2 = K2 * v;                             \
        m0 = mp0 + w0; m1 = mp1 + w1; m2 = mp2 + w2;                             \
        P00 = Pp00 - K0 * K0 * S;                                                \
        P01 = Pp01 - K0 * K1 * S;                                                \
        P02 = Pp02 - K0 * K2 * S;                                                \
        P11 = Pp11 - K1 * K1 * S;                                                \
        P12 = Pp12 - K1 * K2 * S;                                                \
        P22 = Pp22 - K2 * K2 * S;                                                \
        if (STORE) {                                                             \
            g_mfP[iidx(k)] = make_float2(m0, P00);                               \
            if (k == TT - 1) {                                                   \
                g_rec[ridx(2, k)] = make_float4(0.0f, w0, w1, w2);               \
                g_rec[ridx(3, k)] = make_float4(K0, K1, K2, S);                  \
            }                                                                    \
        }                                                                        \
        pw0 = w0; pw1 = w1; pw2 = w2; pK0 = K0; pK1 = K1; pK2 = K2; pS = S;      \
    }

__global__ void forward_kernel(const float* __restrict__ pvar, const float* __restrict__ pls) {
    int c = blockIdx.x * blockDim.x + threadIdx.x;
    if (c >= NCH) return;
    int s = c * CHUNK, e = s + CHUNK;
    int k0 = max(0, s - WARM);

    float var = *pvar;
    float lam = sqrtf(5.0f) / (*pls);
    float lam2 = lam * lam, lam4 = lam2 * lam2;
    float kap = lam2 * (1.0f / 3.0f);
    float pi00 = var, pi02 = -var * kap, pi11 = var * kap, pi22 = var * lam4;

    float m0 = 0.f, m1 = 0.f, m2 = 0.f;
    float P00 = pi00, P01 = 0.f, P02 = pi02, P11 = pi11, P12 = 0.f, P22 = pi22;
    float pw0 = 0.f, pw1 = 0.f, pw2 = 0.f, pK0 = 0.f, pK1 = 0.f, pK2 = 0.f, pS = 1.f;

    // A-pack pipeline, depth 2
    float4 a0 = g_Am[ridx(0, k0)], a1 = g_Am[ridx(1, k0)], a2 = g_Am[ridx(2, k0)];
    int k1i = min(k0 + 1, TT - 1);
    float4 b0 = g_Am[ridx(0, k1i)], b1 = g_Am[ridx(1, k1i)], b2 = g_Am[ridx(2, k1i)];

    // warm-up: branch-free body (no stores)
    for (int k = k0; k < s; ++k) FWD_STEP(0)
    // payload: record stores + smoother gain
    for (int k = s; k < e; ++k) FWD_STEP(1)
}

// Backward delta-form step for slot n; cur0..cur3 = record fields of slot n.
#define BWD_BODY()                                                               \
        float G00 = cur0.x, G01 = cur0.y, G02 = cur0.z, G10 = cur0.w;            \
        float G11 = cur1.x, G12 = cur1.y, G20 = cur1.z, G21 = cur1.w;            \
        float G22 = cur2.x;                                                      \
        float t0 = u0 + wp0, t1 = u1 + wp1, t2 = u2 + wp2;                       \
        float nu0 = G00 * t0 + G01 * t1 + G02 * t2;                              \
        float nu1 = G10 * t0 + G11 * t1 + G12 * t2;                              \
        float nu2 = G20 * t0 + G21 * t1 + G22 * t2;                              \
        float q0 = Sp * Kp0, q1 = Sp * Kp1, q2 = Sp * Kp2;                       \
        float B00 = E00 - q0 * Kp0, B01 = E01 - q0 * Kp1, B02 = E02 - q0 * Kp2;  \
        float B11 = E11 - q1 * Kp1, B12 = E12 - q1 * Kp2, B22 = E22 - q2 * Kp2;  \
        float T00 = G00 * B00 + G01 * B01 + G02 * B02;                           \
        float T01 = G00 * B01 + G01 * B11 + G02 * B12;                           \
        float T02 = G00 * B02 + G01 * B12 + G02 * B22;                           \
        float T10 = G10 * B00 + G11 * B01 + G12 * B02;                           \
        float T11 = G10 * B01 + G11 * B11 + G12 * B12;                           \
        float T12 = G10 * B02 + G11 * B12 + G12 * B22;                           \
        float T20 = G20 * B00 + G21 * B01 + G22 * B02;                           \
        float T21 = G20 * B01 + G21 * B11 + G22 * B12;                           \
        float T22 = G20 * B02 + G21 * B12 + G22 * B22;                           \
        E00 = T00 * G00 + T01 * G01 + T02 * G02;                                 \
        E01 = T00 * G10 + T01 * G11 + T02 * G12;                                 \
        E02 = T00 * G20 + T01 * G21 + T02 * G22;                                 \
        E11 = T10 * G10 + T11 * G11 + T12 * G12;                                 \
        E12 = T10 * G20 + T11 * G21 + T12 * G22;                                 \
        E22 = T20 * G20 + T21 * G21 + T22 * G22;                                 \
        u0 = nu0; u1 = nu1; u2 = nu2;                                            \
        wp0 = cur2.y; wp1 = cur2.z; wp2 = cur2.w;                                \
        Kp0 = cur3.x; Kp1 = cur3.y; Kp2 = cur3.z; Sp = cur3.w;

#define BWD_FETCH()                                                              \
        float4 cur0 = a0, cur1 = a1, cur2 = a2, cur3 = a3;                       \
        a0 = b0; a1 = b1; a2 = b2; a3 = b3;                                      \
        { int q = n - 2;                                                         \
          if (q >= s) {                                                          \
            b0 = g_rec[ridx(0, q)]; b1 = g_rec[ridx(1, q)];                      \
            b2 = g_rec[ridx(2, q)]; b3 = g_rec[ridx(3, q)];                      \
          } }

__global__ void backward_kernel(const float* __restrict__ pmc, float* __restrict__ out, int M) {
    int c = blockIdx.x * blockDim.x + threadIdx.x;
    if (c >= NCH) return;
    int s = c * CHUNK, e = s + CHUNK;
    float mc = *pmc;

    int kinit = min(TT - 1, e - 1 + WARM);

    float u0 = 0.f, u1 = 0.f, u2 = 0.f;
    float E00 = 0.f, E01 = 0.f, E02 = 0.f, E11 = 0.f, E12 = 0.f, E22 = 0.f;
    float wp0, wp1, wp2, Kp0, Kp1, Kp2, Sp;
    {
        float4 f2 = g_rec[ridx(2, kinit)], f3 = g_rec[ridx(3, kinit)];
        wp0 = f2.y; wp1 = f2.z; wp2 = f2.w;
        Kp0 = f3.x; Kp1 = f3.y; Kp2 = f3.z; Sp = f3.w;
        if (c == NCH - 1) {
            int tj = g_tj[TT - 1];
            if (tj >= 0) {
                float2 mf = g_mfP[iidx(TT - 1)];
                out[tj] = mf.x + mc; out[M + tj] = fmaxf(mf.y, 0.0f);
            }
        }
    }

    int n0 = kinit - 1;
    float4 a0 = g_rec[ridx(0, n0)], a1 = g_rec[ridx(1, n0)];
    float4 a2 = g_rec[ridx(2, n0)], a3 = g_rec[ridx(3, n0)];
    int n1i = n0 - 1;
    float4 b0 = g_rec[ridx(0, n1i)], b1 = g_rec[ridx(1, n1i)];
    float4 b2 = g_rec[ridx(2, n1i)], b3 = g_rec[ridx(3, n1i)];

    for (int n = n0; n >= e; --n) {
        BWD_FETCH()
        BWD_BODY()
    }
    for (int n = min(n0, e - 1); n >= s; --n) {
        BWD_FETCH()
        BWD_BODY()
        int tj = g_tj[n];
        if (tj >= 0) {
            float2 mf = g_mfP[iidx(n)];
            out[tj] = mf.x + u0 + mc;
            out[M + tj] = fmaxf(mf.y + E00, 0.0f);
        }
    }
}

extern "C" void kernel_launch(void* const* d_in, const int* in_sizes, int n_in,
                              void* d_out, int out_size) {
    const float* times = (const float*)d_in[0];
    const float* tstar = (const float*)d_in[1];
    const float* n1    = (const float*)d_in[2];
    const float* n2    = (const float*)d_in[3];
    const float* pvar  = (const float*)d_in[4];
    const float* pls   = (const float*)d_in[5];
    const float* pmc   = (const float*)d_in[6];
    int N = in_sizes[0];
    int M = in_sizes[1];
    int total = N + M;

    merge_kernel<<<(total + 255) / 256, 256>>>(times, tstar, n1, n2, pmc, N, M);
    amat_kernel<<<(TT + 255) / 256, 256>>>(pls);
    forward_kernel<<<(NCH + 31) / 32, 32>>>(pvar, pls);
    backward_kernel<<<(NCH + 31) / 32, 32>>>(pmc, (float*)d_out, M);
}